// round 15
// baseline (speedup 1.0000x reference)
#include <cuda_runtime.h>
#include <math.h>
#include <stdint.h>

// Problem dims (fixed)
#define S_   512
#define B_   64
#define IN_  512
#define H_   1024
#define OUT_ 512
#define MB_  (S_ * B_)   // 32768 rows in all time-parallel GEMMs
#define H3_  (3 * H_)    // 3072 fused projection columns
#define BH_  (B_ * H_)
#define BH3_ (B_ * H3_)

// ---------------------------------------------------------------------------
// Scratch (__device__ globals; no cudaMalloc allowed)
// ---------------------------------------------------------------------------
__device__ float g_proj[(size_t)MB_ * H3_];   // fused xa|xc|xh (384 MB)
__device__ float g_y  [(size_t)MB_ * H_];     // layer outputs (tf32-rounded)
__device__ float g_xt [(size_t)MB_ * IN_];    // x tf32-rounded
__device__ float g_bt0[(size_t)H3_ * IN_];    // [3H][IN] W^T (tf32)
__device__ float g_bt1[(size_t)H3_ * H_];     // [3H][H]  W^T (tf32)
__device__ float g_btd[(size_t)OUT_ * H_];    // [OUT][H] Wdec^T (tf32)

// ---------------------------------------------------------------------------
// Inline PTX (sm_80-compatible: cp.async + ldmatrix + mma.sync tf32)
// ---------------------------------------------------------------------------
__device__ __forceinline__ uint32_t smem_u32(const void* p) {
    uint32_t a;
    asm("{ .reg .u64 t; cvta.to.shared.u64 t, %1; cvt.u32.u64 %0, t; }" : "=r"(a) : "l"(p));
    return a;
}
#define CP_ASYNC16(dst, src) \
    asm volatile("cp.async.cg.shared.global [%0], [%1], 16;" :: "r"(dst), "l"(src) : "memory")
#define CP_COMMIT() asm volatile("cp.async.commit_group;" ::: "memory")
#define CP_WAIT(n)  asm volatile("cp.async.wait_group %0;" :: "n"(n) : "memory")

__device__ __forceinline__ void ldm_x4(uint32_t* r, uint32_t addr) {
    asm volatile("ldmatrix.sync.aligned.m8n8.x4.shared.b16 {%0,%1,%2,%3}, [%4];"
        : "=r"(r[0]), "=r"(r[1]), "=r"(r[2]), "=r"(r[3]) : "r"(addr));
}
__device__ __forceinline__ uint32_t f2tf32(float x) {
    uint32_t r;
    asm("cvt.rna.tf32.f32 %0, %1;" : "=r"(r) : "f"(x));
    return r;
}
__device__ __forceinline__ void mma_tf32(float* d, const uint32_t* a, const uint32_t* b) {
    asm volatile(
        "mma.sync.aligned.m16n8k8.row.col.f32.tf32.tf32.f32 "
        "{%0,%1,%2,%3}, {%4,%5,%6,%7}, {%8,%9}, {%0,%1,%2,%3};"
        : "+f"(d[0]), "+f"(d[1]), "+f"(d[2]), "+f"(d[3])
        : "r"(a[0]), "r"(a[1]), "r"(a[2]), "r"(a[3]), "r"(b[0]), "r"(b[1]));
}

// ---------------------------------------------------------------------------
// TF32 tensor-core GEMM: C = A @ Bt^T + bias3
// 256x128 block tile, BK=32, 256 threads = 8 warps in 4x2 grid of 64x64
// warp tiles. Per-k-tile smem traffic 176KB over 2048 tensor cycles =
// 86 B/cyc < 128 B/cyc crossbar -> smem no longer the ceiling.
// 4-stage cp.async pipeline (48KB/stage, 192KB -> 1 CTA/SM, 8 warps).
// Chunk-XOR swizzle: 16B chunk c of row r at c ^ (r&7).
// Fragments via ldmatrix.x4 (tf32-as-2xb16). bias3: slabs by col>>10.
// M%256==0, N%128==0, K%32==0 everywhere; no guards.
// ---------------------------------------------------------------------------
#define STAGES 4
#define STAGE_BYTES 49152u              // A 32KB + B 16KB
#define GEMM_SMEM (STAGES * STAGE_BYTES)

__device__ __forceinline__ void stage_load(const float* __restrict__ A,
                                           const float* __restrict__ Bt,
                                           int K, uint32_t stage_base,
                                           int bm, int bn, int k0, int tid) {
#pragma unroll
    for (int i = 0; i < 8; i++) {                 // A: 256 rows x 8 chunks
        int q = tid + i * 256;
        int r = q >> 3, c = q & 7;
        const float* g = A + (size_t)(bm + r) * K + k0 + c * 4;
        CP_ASYNC16(stage_base + (uint32_t)(r * 128 + ((c ^ (r & 7)) * 16)), g);
    }
#pragma unroll
    for (int i = 0; i < 4; i++) {                 // B: 128 rows x 8 chunks
        int q = tid + i * 256;
        int r = q >> 3, c = q & 7;
        const float* g = Bt + (size_t)(bn + r) * K + k0 + c * 4;
        CP_ASYNC16(stage_base + 32768u + (uint32_t)(r * 128 + ((c ^ (r & 7)) * 16)), g);
    }
}

__global__ __launch_bounds__(256, 1)
void gemm_tf32(const float* __restrict__ A, const float* __restrict__ Bt,
               const float* __restrict__ bias_a, const float* __restrict__ bias_b,
               const float* __restrict__ bias_c,
               float* __restrict__ C, int N, int K)
{
    extern __shared__ char smraw[];
    const uint32_t smbase = smem_u32(smraw);

    const int tid  = threadIdx.x;
    const int w    = tid >> 5, lane = tid & 31;
    const int wm   = (w >> 1) * 64;      // 0/64/128/192
    const int wn   = (w & 1) * 64;       // 0/64
    const int bm   = blockIdx.y * 256;
    const int bn   = blockIdx.x * 128;
    const int nkt  = K / 32;
    const int r0   = lane >> 2;          // 0..7 (epilogue)
    const int c0   = lane & 3;           // 0..3 (epilogue)

    // ldmatrix lane-address components (row&7 == lane&7 for all tiles)
    const uint32_t s7  = (uint32_t)(lane & 7);
    const int      rAl = (lane & 7) + ((lane >> 3) & 1) * 8;   // A local row
    const uint32_t cpA = (uint32_t)(lane >> 4);                // chunk parity
    const int      rBl = (lane & 7) + ((lane >> 4) & 1) * 8;   // B local row
    const uint32_t cpB = (uint32_t)((lane >> 3) & 1);

    float acc[4][8][4];
#pragma unroll
    for (int mi = 0; mi < 4; mi++)
#pragma unroll
        for (int ni = 0; ni < 8; ni++)
#pragma unroll
            for (int j = 0; j < 4; j++) acc[mi][ni][j] = 0.f;

    // prologue: 3 stages in flight
#pragma unroll
    for (int t = 0; t < STAGES - 1; t++) {
        stage_load(A, Bt, K, smbase + (uint32_t)t * STAGE_BYTES, bm, bn, t * 32, tid);
        CP_COMMIT();
    }

    for (int t = 0; t < nkt; t++) {
        const int s = t & 3;
        CP_WAIT(2);
        __syncthreads();

        if (t + STAGES - 1 < nkt)
            stage_load(A, Bt, K, smbase + (uint32_t)((t + 3) & 3) * STAGE_BYTES,
                       bm, bn, (t + 3) * 32, tid);
        CP_COMMIT();

        const uint32_t abase = smbase + (uint32_t)s * STAGE_BYTES;
        const uint32_t bbase = abase + 32768u;
        const uint32_t aRow  = abase + (uint32_t)(wm + rAl) * 128u;
        const uint32_t bRow  = bbase + (uint32_t)(wn + rBl) * 128u;

#pragma unroll
        for (int ks = 0; ks < 4; ks++) {
            const uint32_t offA = (((uint32_t)(2 * ks) + cpA) ^ s7) * 16u;
            const uint32_t offB = (((uint32_t)(2 * ks) + cpB) ^ s7) * 16u;

            uint32_t afr[4][4], bfr[4][4];
#pragma unroll
            for (int mi = 0; mi < 4; mi++)
                ldm_x4(afr[mi], aRow + (uint32_t)(mi * 2048) + offA);
#pragma unroll
            for (int n4 = 0; n4 < 4; n4++)
                ldm_x4(bfr[n4], bRow + (uint32_t)(n4 * 2048) + offB);

#pragma unroll
            for (int mi = 0; mi < 4; mi++)
#pragma unroll
                for (int ni = 0; ni < 8; ni++)
                    mma_tf32(acc[mi][ni], afr[mi], &bfr[ni >> 1][(ni & 1) * 2]);
        }
    }

    // epilogue with fused 3-slab bias select
#pragma unroll
    for (int mi = 0; mi < 4; mi++) {
        const int row = bm + wm + mi * 16 + r0;
#pragma unroll
        for (int ni = 0; ni < 8; ni++) {
            const int col = bn + wn + ni * 8 + c0 * 2;
            const int slab = col >> 10;
            const float* bp = (slab == 0) ? bias_a : (slab == 1) ? bias_b : bias_c;
            const int ci = col & (H_ - 1);
            const float b0 = bp[ci], b1 = bp[ci + 1];
            float2 v0 = make_float2(acc[mi][ni][0] + b0, acc[mi][ni][1] + b1);
            float2 v1 = make_float2(acc[mi][ni][2] + b0, acc[mi][ni][3] + b1);
            *(float2*)(C + (size_t)row * N + col) = v0;
            *(float2*)(C + (size_t)(row + 8) * N + col) = v1;
        }
    }
}

// ---------------------------------------------------------------------------
// cvt kernel: x -> tf32-rounded xt
// ---------------------------------------------------------------------------
__global__ __launch_bounds__(256)
void cvt_tf32(const float* __restrict__ in, float* __restrict__ out)
{
    size_t i = ((size_t)blockIdx.x * 256 + threadIdx.x) * 4;
    float4 v = *(const float4*)(in + i);
    v.x = __uint_as_float(f2tf32(v.x));
    v.y = __uint_as_float(f2tf32(v.y));
    v.z = __uint_as_float(f2tf32(v.z));
    v.w = __uint_as_float(f2tf32(v.w));
    *(float4*)(out + i) = v;
}

// ---------------------------------------------------------------------------
// Weight transpose kernel (bid-offset; split into 2 launches so gemm0 is
// the 4th overall launch for ncu):
// ---------------------------------------------------------------------------
#define PREP_T0   1536
#define PREP_T1   4608
#define PREP_TD   5120

__global__ __launch_bounds__(256)
void tweights(const float* __restrict__ Ua0, const float* __restrict__ Uc0,
              const float* __restrict__ Uh0,
              const float* __restrict__ Ua1, const float* __restrict__ Uc1,
              const float* __restrict__ Uh1,
              const float* __restrict__ Wdec,
              float* __restrict__ bt0, float* __restrict__ bt1,
              float* __restrict__ btd, int bid_off)
{
    const int bid = blockIdx.x + bid_off;
    const int tid = threadIdx.x;

    const float* in;
    float* out;
    int R, C, tile;
    if (bid < PREP_T0) {
        int which = bid / 512; tile = bid - which * 512;
        in = (which == 0) ? Ua0 : (which == 1) ? Uc0 : Uh0;
        out = bt0 + (size_t)which * H_ * IN_;
        R = IN_; C = H_;
    } else if (bid < PREP_T1) {
        int j = bid - PREP_T0;
        int which = j / 1024; tile = j - which * 1024;
        in = (which == 0) ? Ua1 : (which == 1) ? Uc1 : Uh1;
        out = bt1 + (size_t)which * H_ * H_;
        R = H_; C = H_;
    } else {
        tile = bid - PREP_T1;
        in = Wdec; out = btd;
        R = H_; C = OUT_;
    }
    const int tilesX = C / 32;
    const int cx = tile % tilesX, cy = tile / tilesX;
    const int r0 = cy * 32, c0 = cx * 32;
    const int tx = tid & 31, ty = tid >> 5;   // ty 0..7

    __shared__ float t[32][33];
#pragma unroll
    for (int i = 0; i < 32; i += 8)
        t[ty + i][tx] = in[(size_t)(r0 + ty + i) * C + c0 + tx];
    __syncthreads();
#pragma unroll
    for (int i = 0; i < 32; i += 8)
        out[(size_t)(c0 + ty + i) * R + r0 + tx] =
            __uint_as_float(f2tf32(t[tx][ty + i]));
}

// ---------------------------------------------------------------------------
// BRC scan (R14 measured-best): ILP-1, 8-deep prefetch ring, fast
// tanh/sigmoid (__expf-based), writes tf32-rounded y.
// proj row layout [S,B,3H]: xa|xc|xh.
// ---------------------------------------------------------------------------
__device__ __forceinline__ float fast_tanh(float x) {
    float e = __expf(2.f * x);
    return 1.f - __fdividef(2.f, e + 1.f);
}
__device__ __forceinline__ float fast_sigmoid(float x) {
    return __fdividef(1.f, 1.f + __expf(-x));
}

__global__ __launch_bounds__(128)
void brc_scan(const float* __restrict__ proj, const float* __restrict__ h0,
              const float* __restrict__ wa, const float* __restrict__ wc,
              float* __restrict__ y, float* __restrict__ h_last)
{
    const int idx = blockIdx.x * 128 + threadIdx.x;   // b*H + h
    const int b  = idx >> 10;
    const int hi = idx & (H_ - 1);

    float h = h0[idx];
    const float wav = wa[hi];
    const float wcv = wc[hi];

    const size_t pbase = (size_t)b * H3_ + hi;

    float bufa[8], bufc[8], bufh[8];
#pragma unroll
    for (int j = 0; j < 8; j++) {
        size_t o = pbase + (size_t)j * BH3_;
        bufa[j] = proj[o]; bufc[j] = proj[o + H_]; bufh[j] = proj[o + 2 * H_];
    }

    size_t yoff = idx;
    for (int so = 0; so < S_; so += 8) {
        const bool pf = (so + 8 < S_);
#pragma unroll
        for (int j = 0; j < 8; j++) {
            float va = bufa[j], vc = bufc[j], vh = bufh[j];
            if (pf) {
                size_t o = pbase + (size_t)(so + j + 8) * BH3_;
                bufa[j] = proj[o]; bufc[j] = proj[o + H_]; bufh[j] = proj[o + 2 * H_];
            }
            float a = 1.f + fast_tanh(va + wav * h);
            float c = fast_sigmoid(vc + wcv * h);
            h = c * h + (1.f - c) * fast_tanh(vh + a * h);
            y[yoff] = __uint_as_float(f2tf32(h));
            yoff += BH_;
        }
    }
    h_last[idx] = h;
}

// ---------------------------------------------------------------------------
// Launch. Order: cvt(1), twA(2), twB(3), gemm0(4 <- ncu-profiled), scan0(5),
// gemm1(6), scan1(7), gemmd(8).
// ---------------------------------------------------------------------------
extern "C" void kernel_launch(void* const* d_in, const int* in_sizes, int n_in,
                              void* d_out, int out_size)
{
    const float* x    = (const float*)d_in[0];
    const float* h0   = (const float*)d_in[1];
    const float* Ua0  = (const float*)d_in[2];
    const float* Uc0  = (const float*)d_in[3];
    const float* Uh0  = (const float*)d_in[4];
    const float* wa0  = (const float*)d_in[5];
    const float* wc0  = (const float*)d_in[6];
    const float* ba0  = (const float*)d_in[7];
    const float* bc0  = (const float*)d_in[8];
    const float* bh0  = (const float*)d_in[9];
    const float* Ua1  = (const float*)d_in[10];
    const float* Uc1  = (const float*)d_in[11];
    const float* Uh1  = (const float*)d_in[12];
    const float* wa1  = (const float*)d_in[13];
    const float* wc1  = (const float*)d_in[14];
    const float* ba1  = (const float*)d_in[15];
    const float* bc1  = (const float*)d_in[16];
    const float* bh1  = (const float*)d_in[17];
    const float* Wdec = (const float*)d_in[18];
    const float* bdec = (const float*)d_in[19];

    float* out    = (float*)d_out;
    float* hidden = out + (size_t)S_ * B_ * OUT_;

    float *proj, *y, *xt, *bt0, *bt1, *btd;
    cudaGetSymbolAddress((void**)&proj, g_proj);
    cudaGetSymbolAddress((void**)&y,    g_y);
    cudaGetSymbolAddress((void**)&xt,   g_xt);
    cudaGetSymbolAddress((void**)&bt0,  g_bt0);
    cudaGetSymbolAddress((void**)&bt1,  g_bt1);
    cudaGetSymbolAddress((void**)&btd,  g_btd);

    cudaFuncSetAttribute(gemm_tf32, cudaFuncAttributeMaxDynamicSharedMemorySize,
                         GEMM_SMEM);

    const dim3 gblk(256);
    const dim3 scanGrid(BH_ / 128), sblk(128);

    // 1: x -> tf32
    cvt_tf32<<<(MB_ * IN_) / 1024, 256>>>(x, xt);

    // 2+3: weight transposes split so gemm0 is the 4th launch
    tweights<<<PREP_T0, 256>>>(Ua0, Uc0, Uh0, Ua1, Uc1, Uh1, Wdec,
                               bt0, bt1, btd, 0);
    tweights<<<PREP_TD - PREP_T0, 256>>>(Ua0, Uc0, Uh0, Ua1, Uc1, Uh1, Wdec,
                                         bt0, bt1, btd, PREP_T0);

    // 4: layer-0 fused projections [32768,512] @ [512,3072]  <- profiled
    gemm_tf32<<<dim3(H3_ / 128, MB_ / 256), gblk, GEMM_SMEM>>>(
        xt, bt0, ba0, bc0, bh0, proj, H3_, IN_);

    // 5: layer-0 scan
    brc_scan<<<scanGrid, sblk>>>(proj, h0, wa0, wc0, y, hidden);

    // 6: layer-1 fused projections [32768,1024] @ [1024,3072]
    gemm_tf32<<<dim3(H3_ / 128, MB_ / 256), gblk, GEMM_SMEM>>>(
        y, bt1, ba1, bc1, bh1, proj, H3_, H_);

    // 7: layer-1 scan
    brc_scan<<<scanGrid, sblk>>>(proj, h0 + (size_t)BH_, wa1, wc1, y,
                                 hidden + (size_t)BH_);

    // 8: decoder [32768,1024] @ [1024,512]
    gemm_tf32<<<dim3(OUT_ / 128, MB_ / 256), gblk, GEMM_SMEM>>>(
        y, btd, bdec, bdec, bdec, out, OUT_, H_);
}

// round 16
// speedup vs baseline: 1.8477x; 1.8477x over previous
#include <cuda_runtime.h>
#include <cuda_fp16.h>
#include <math.h>
#include <stdint.h>

// Problem dims (fixed)
#define S_   512
#define B_   64
#define IN_  512
#define H_   1024
#define OUT_ 512
#define MB_  (S_ * B_)   // 32768 rows in all time-parallel GEMMs
#define H3_  (3 * H_)    // 3072 fused projection columns
#define BH_  (B_ * H_)
#define BH3_ (B_ * H3_)

// ---------------------------------------------------------------------------
// Scratch (__device__ globals; no cudaMalloc allowed)
// ---------------------------------------------------------------------------
__device__ float  g_proj[(size_t)MB_ * H3_];  // fused xa|xc|xh (384 MB, fp32)
__device__ __half g_y  [(size_t)MB_ * H_];    // layer outputs (fp16)
__device__ __half g_xt [(size_t)MB_ * IN_];   // x in fp16
__device__ __half g_bt0[(size_t)H3_ * IN_];   // [3H][IN] W^T (fp16)
__device__ __half g_bt1[(size_t)H3_ * H_];    // [3H][H]  W^T (fp16)
__device__ __half g_btd[(size_t)OUT_ * H_];   // [OUT][H] Wdec^T (fp16)

// ---------------------------------------------------------------------------
// Inline PTX (sm_80-compatible: cp.async + ldmatrix + mma.sync fp16)
// ---------------------------------------------------------------------------
__device__ __forceinline__ uint32_t smem_u32(const void* p) {
    uint32_t a;
    asm("{ .reg .u64 t; cvta.to.shared.u64 t, %1; cvt.u32.u64 %0, t; }" : "=r"(a) : "l"(p));
    return a;
}
#define CP_ASYNC16(dst, src) \
    asm volatile("cp.async.cg.shared.global [%0], [%1], 16;" :: "r"(dst), "l"(src) : "memory")
#define CP_COMMIT() asm volatile("cp.async.commit_group;" ::: "memory")
#define CP_WAIT(n)  asm volatile("cp.async.wait_group %0;" :: "n"(n) : "memory")

__device__ __forceinline__ void ldm_x4(uint32_t* r, uint32_t addr) {
    asm volatile("ldmatrix.sync.aligned.m8n8.x4.shared.b16 {%0,%1,%2,%3}, [%4];"
        : "=r"(r[0]), "=r"(r[1]), "=r"(r[2]), "=r"(r[3]) : "r"(addr));
}
__device__ __forceinline__ void mma_f16(float* d, const uint32_t* a, const uint32_t* b) {
    asm volatile(
        "mma.sync.aligned.m16n8k16.row.col.f32.f16.f16.f32 "
        "{%0,%1,%2,%3}, {%4,%5,%6,%7}, {%8,%9}, {%0,%1,%2,%3};"
        : "+f"(d[0]), "+f"(d[1]), "+f"(d[2]), "+f"(d[3])
        : "r"(a[0]), "r"(a[1]), "r"(a[2]), "r"(a[3]), "r"(b[0]), "r"(b[1]));
}

// ---------------------------------------------------------------------------
// FP16 tensor-core GEMM: C[fp32] = A[fp16] @ Bt[fp16]^T + bias3
// 128x128 block tile, BK=64, 128 threads = 4 warps (2x2 of 64x64 warp
// tiles). 3-stage cp.async pipeline (32KB/stage: A 16KB + B 16KB; 96KB
// -> 2 CTAs/SM, the measured-mandatory config).
// Smem rows: 128 rows x 128B (64 fp16). Chunk-XOR swizzle: 16B chunk c of
// row r at c ^ (r&7) — identical geometry to the validated tf32 kernel.
// Per BK=64 k-tile: 4 k16-steps; chunk pair (2ks, 2ks+1).
// A lane map (= tf32 kernel, validated): rAl=(lane&7)+((lane>>3)&1)*8,
// cpA=lane>>4. B lane map (= R6 bf16 kernel, validated):
// rBl=(lane&7)+((lane>>4)&1)*8, cpB=(lane>>3)&1.
// bias3: three H_-sized slabs selected by col>>10.
// M%128==0, N%128==0, K%64==0 everywhere; no guards.
// ---------------------------------------------------------------------------
#define STAGES 3
#define STAGE_BYTES 32768u
#define GEMM_SMEM (STAGES * STAGE_BYTES)

__device__ __forceinline__ void stage_load(const __half* __restrict__ A,
                                           const __half* __restrict__ Bt,
                                           int K, uint32_t stage_base,
                                           int bm, int bn, int k0, int tid) {
#pragma unroll
    for (int i = 0; i < 8; i++) {                 // A: 128 rows x 8 chunks
        int q = tid + i * 128;
        int r = q >> 3, c = q & 7;
        const __half* g = A + (size_t)(bm + r) * K + k0 + c * 8;
        CP_ASYNC16(stage_base + (uint32_t)(r * 128 + ((c ^ (r & 7)) * 16)), g);
    }
#pragma unroll
    for (int i = 0; i < 8; i++) {                 // B: 128 rows x 8 chunks
        int q = tid + i * 128;
        int r = q >> 3, c = q & 7;
        const __half* g = Bt + (size_t)(bn + r) * K + k0 + c * 8;
        CP_ASYNC16(stage_base + 16384u + (uint32_t)(r * 128 + ((c ^ (r & 7)) * 16)), g);
    }
}

__global__ __launch_bounds__(128, 2)
void gemm_f16(const __half* __restrict__ A, const __half* __restrict__ Bt,
              const float* __restrict__ bias_a, const float* __restrict__ bias_b,
              const float* __restrict__ bias_c,
              float* __restrict__ C, int N, int K)
{
    extern __shared__ char smraw[];
    const uint32_t smbase = smem_u32(smraw);

    const int tid  = threadIdx.x;
    const int w    = tid >> 5, lane = tid & 31;
    const int wm   = (w >> 1) * 64;      // 0/64
    const int wn   = (w & 1) * 64;       // 0/64
    const int bm   = blockIdx.y * 128;
    const int bn   = blockIdx.x * 128;
    const int nkt  = K / 64;
    const int r0   = lane >> 2;          // 0..7 (epilogue)
    const int c0   = lane & 3;           // 0..3 (epilogue)

    // ldmatrix lane-address components (row&7 == lane&7 for all tiles)
    const uint32_t s7  = (uint32_t)(lane & 7);
    const int      rAl = (lane & 7) + ((lane >> 3) & 1) * 8;   // A local row
    const uint32_t cpA = (uint32_t)(lane >> 4);                // chunk parity
    const int      rBl = (lane & 7) + ((lane >> 4) & 1) * 8;   // B local row
    const uint32_t cpB = (uint32_t)((lane >> 3) & 1);

    float acc[4][8][4];
#pragma unroll
    for (int mi = 0; mi < 4; mi++)
#pragma unroll
        for (int ni = 0; ni < 8; ni++)
#pragma unroll
            for (int j = 0; j < 4; j++) acc[mi][ni][j] = 0.f;

    // prologue: 2 stages in flight
#pragma unroll
    for (int t = 0; t < STAGES - 1; t++) {
        stage_load(A, Bt, K, smbase + (uint32_t)t * STAGE_BYTES, bm, bn, t * 64, tid);
        CP_COMMIT();
    }

    for (int t = 0; t < nkt; t++) {
        const int s = t % 3;
        CP_WAIT(1);
        __syncthreads();

        if (t + STAGES - 1 < nkt)
            stage_load(A, Bt, K, smbase + (uint32_t)((t + 2) % 3) * STAGE_BYTES,
                       bm, bn, (t + 2) * 64, tid);
        CP_COMMIT();

        const uint32_t abase = smbase + (uint32_t)s * STAGE_BYTES;
        const uint32_t bbase = abase + 16384u;
        const uint32_t aRow  = abase + (uint32_t)(wm + rAl) * 128u;
        const uint32_t bRow  = bbase + (uint32_t)(wn + rBl) * 128u;

#pragma unroll
        for (int ks = 0; ks < 4; ks++) {            // 4 x k16 per BK=64 tile
            const uint32_t offA = (((uint32_t)(2 * ks) + cpA) ^ s7) * 16u;
            const uint32_t offB = (((uint32_t)(2 * ks) + cpB) ^ s7) * 16u;

            uint32_t afr[4][4], bfr[4][4];
#pragma unroll
            for (int mi = 0; mi < 4; mi++)
                ldm_x4(afr[mi], aRow + (uint32_t)(mi * 2048) + offA);
#pragma unroll
            for (int n4 = 0; n4 < 4; n4++)
                ldm_x4(bfr[n4], bRow + (uint32_t)(n4 * 2048) + offB);

#pragma unroll
            for (int mi = 0; mi < 4; mi++)
#pragma unroll
                for (int ni = 0; ni < 8; ni++)
                    mma_f16(acc[mi][ni], afr[mi], &bfr[ni >> 1][(ni & 1) * 2]);
        }
    }

    // epilogue with fused 3-slab bias select (fp32 out)
#pragma unroll
    for (int mi = 0; mi < 4; mi++) {
        const int row = bm + wm + mi * 16 + r0;
#pragma unroll
        for (int ni = 0; ni < 8; ni++) {
            const int col = bn + wn + ni * 8 + c0 * 2;
            const int slab = col >> 10;
            const float* bp = (slab == 0) ? bias_a : (slab == 1) ? bias_b : bias_c;
            const int ci = col & (H_ - 1);
            const float b0 = bp[ci], b1 = bp[ci + 1];
            float2 v0 = make_float2(acc[mi][ni][0] + b0, acc[mi][ni][1] + b1);
            float2 v1 = make_float2(acc[mi][ni][2] + b0, acc[mi][ni][3] + b1);
            *(float2*)(C + (size_t)row * N + col) = v0;
            *(float2*)(C + (size_t)(row + 8) * N + col) = v1;
        }
    }
}

// ---------------------------------------------------------------------------
// cvt kernel: x fp32 -> fp16
// ---------------------------------------------------------------------------
__global__ __launch_bounds__(256)
void cvt_f16(const float* __restrict__ in, __half* __restrict__ out)
{
    size_t i = ((size_t)blockIdx.x * 256 + threadIdx.x) * 4;
    float4 v = *(const float4*)(in + i);
    __half2* o = (__half2*)(out + i);
    o[0] = __floats2half2_rn(v.x, v.y);
    o[1] = __floats2half2_rn(v.z, v.w);
}

// ---------------------------------------------------------------------------
// Weight transpose kernel (bid-offset; split into 2 launches so gemm0 is
// the 4th overall launch for ncu). out[c][r] = fp16(in[r][c]).
// ---------------------------------------------------------------------------
#define PREP_T0   1536
#define PREP_T1   4608
#define PREP_TD   5120

__global__ __launch_bounds__(256)
void tweights(const float* __restrict__ Ua0, const float* __restrict__ Uc0,
              const float* __restrict__ Uh0,
              const float* __restrict__ Ua1, const float* __restrict__ Uc1,
              const float* __restrict__ Uh1,
              const float* __restrict__ Wdec,
              __half* __restrict__ bt0, __half* __restrict__ bt1,
              __half* __restrict__ btd, int bid_off)
{
    const int bid = blockIdx.x + bid_off;
    const int tid = threadIdx.x;

    const float* in;
    __half* out;
    int R, C, tile;
    if (bid < PREP_T0) {
        int which = bid / 512; tile = bid - which * 512;
        in = (which == 0) ? Ua0 : (which == 1) ? Uc0 : Uh0;
        out = bt0 + (size_t)which * H_ * IN_;
        R = IN_; C = H_;
    } else if (bid < PREP_T1) {
        int j = bid - PREP_T0;
        int which = j / 1024; tile = j - which * 1024;
        in = (which == 0) ? Ua1 : (which == 1) ? Uc1 : Uh1;
        out = bt1 + (size_t)which * H_ * H_;
        R = H_; C = H_;
    } else {
        tile = bid - PREP_T1;
        in = Wdec; out = btd;
        R = H_; C = OUT_;
    }
    const int tilesX = C / 32;
    const int cx = tile % tilesX, cy = tile / tilesX;
    const int r0 = cy * 32, c0 = cx * 32;
    const int tx = tid & 31, ty = tid >> 5;   // ty 0..7

    __shared__ float t[32][33];
#pragma unroll
    for (int i = 0; i < 32; i += 8)
        t[ty + i][tx] = in[(size_t)(r0 + ty + i) * C + c0 + tx];
    __syncthreads();
#pragma unroll
    for (int i = 0; i < 32; i += 8)
        out[(size_t)(c0 + ty + i) * R + r0 + tx] = __float2half_rn(t[tx][ty + i]);
}

// ---------------------------------------------------------------------------
// BRC scan (R14 measured-best): ILP-1, 8-deep prefetch ring, fast
// tanh/sigmoid (__expf-based). Reads proj fp32, writes y as fp16.
// proj row layout [S,B,3H]: xa|xc|xh.
// ---------------------------------------------------------------------------
__device__ __forceinline__ float fast_tanh(float x) {
    float e = __expf(2.f * x);
    return 1.f - __fdividef(2.f, e + 1.f);
}
__device__ __forceinline__ float fast_sigmoid(float x) {
    return __fdividef(1.f, 1.f + __expf(-x));
}

__global__ __launch_bounds__(128)
void brc_scan(const float* __restrict__ proj, const float* __restrict__ h0,
              const float* __restrict__ wa, const float* __restrict__ wc,
              __half* __restrict__ y, float* __restrict__ h_last)
{
    const int idx = blockIdx.x * 128 + threadIdx.x;   // b*H + h
    const int b  = idx >> 10;
    const int hi = idx & (H_ - 1);

    float h = h0[idx];
    const float wav = wa[hi];
    const float wcv = wc[hi];

    const size_t pbase = (size_t)b * H3_ + hi;

    float bufa[8], bufc[8], bufh[8];
#pragma unroll
    for (int j = 0; j < 8; j++) {
        size_t o = pbase + (size_t)j * BH3_;
        bufa[j] = proj[o]; bufc[j] = proj[o + H_]; bufh[j] = proj[o + 2 * H_];
    }

    size_t yoff = idx;
    for (int so = 0; so < S_; so += 8) {
        const bool pf = (so + 8 < S_);
#pragma unroll
        for (int j = 0; j < 8; j++) {
            float va = bufa[j], vc = bufc[j], vh = bufh[j];
            if (pf) {
                size_t o = pbase + (size_t)(so + j + 8) * BH3_;
                bufa[j] = proj[o]; bufc[j] = proj[o + H_]; bufh[j] = proj[o + 2 * H_];
            }
            float a = 1.f + fast_tanh(va + wav * h);
            float c = fast_sigmoid(vc + wcv * h);
            h = c * h + (1.f - c) * fast_tanh(vh + a * h);
            y[yoff] = __float2half_rn(h);
            yoff += BH_;
        }
    }
    h_last[idx] = h;
}

// ---------------------------------------------------------------------------
// Launch. Order: cvt(1), twA(2), twB(3), gemm0(4 <- ncu-profiled), scan0(5),
// gemm1(6), scan1(7), gemmd(8).
// ---------------------------------------------------------------------------
extern "C" void kernel_launch(void* const* d_in, const int* in_sizes, int n_in,
                              void* d_out, int out_size)
{
    const float* x    = (const float*)d_in[0];
    const float* h0   = (const float*)d_in[1];
    const float* Ua0  = (const float*)d_in[2];
    const float* Uc0  = (const float*)d_in[3];
    const float* Uh0  = (const float*)d_in[4];
    const float* wa0  = (const float*)d_in[5];
    const float* wc0  = (const float*)d_in[6];
    const float* ba0  = (const float*)d_in[7];
    const float* bc0  = (const float*)d_in[8];
    const float* bh0  = (const float*)d_in[9];
    const float* Ua1  = (const float*)d_in[10];
    const float* Uc1  = (const float*)d_in[11];
    const float* Uh1  = (const float*)d_in[12];
    const float* wa1  = (const float*)d_in[13];
    const float* wc1  = (const float*)d_in[14];
    const float* ba1  = (const float*)d_in[15];
    const float* bc1  = (const float*)d_in[16];
    const float* bh1  = (const float*)d_in[17];
    const float* Wdec = (const float*)d_in[18];
    const float* bdec = (const float*)d_in[19];

    float* out    = (float*)d_out;
    float* hidden = out + (size_t)S_ * B_ * OUT_;

    float* proj;
    __half *y, *xt, *bt0, *bt1, *btd;
    cudaGetSymbolAddress((void**)&proj, g_proj);
    cudaGetSymbolAddress((void**)&y,    g_y);
    cudaGetSymbolAddress((void**)&xt,   g_xt);
    cudaGetSymbolAddress((void**)&bt0,  g_bt0);
    cudaGetSymbolAddress((void**)&bt1,  g_bt1);
    cudaGetSymbolAddress((void**)&btd,  g_btd);

    cudaFuncSetAttribute(gemm_f16, cudaFuncAttributeMaxDynamicSharedMemorySize,
                         GEMM_SMEM);

    const dim3 gblk(128);
    const dim3 scanGrid(BH_ / 128), sblk(128);

    // 1: x -> fp16
    cvt_f16<<<(MB_ * IN_) / 1024, 256>>>(x, xt);

    // 2+3: weight transposes split so gemm0 is the 4th launch
    tweights<<<PREP_T0, 256>>>(Ua0, Uc0, Uh0, Ua1, Uc1, Uh1, Wdec,
                               bt0, bt1, btd, 0);
    tweights<<<PREP_TD - PREP_T0, 256>>>(Ua0, Uc0, Uh0, Ua1, Uc1, Uh1, Wdec,
                                         bt0, bt1, btd, PREP_T0);

    // 4: layer-0 fused projections [32768,512] @ [512,3072]  <- profiled
    gemm_f16<<<dim3(H3_ / 128, MB_ / 128), gblk, GEMM_SMEM>>>(
        xt, bt0, ba0, bc0, bh0, proj, H3_, IN_);

    // 5: layer-0 scan
    brc_scan<<<scanGrid, sblk>>>(proj, h0, wa0, wc0, y, hidden);

    // 6: layer-1 fused projections [32768,1024] @ [1024,3072]
    gemm_f16<<<dim3(H3_ / 128, MB_ / 128), gblk, GEMM_SMEM>>>(
        y, bt1, ba1, bc1, bh1, proj, H3_, H_);

    // 7: layer-1 scan
    brc_scan<<<scanGrid, sblk>>>(proj, h0 + (size_t)BH_, wa1, wc1, y,
                                 hidden + (size_t)BH_);

    // 8: decoder [32768,1024] @ [1024,512]
    gemm_f16<<<dim3(OUT_ / 128, MB_ / 128), gblk, GEMM_SMEM>>>(
        y, btd, bdec, bdec, bdec, out, OUT_, H_);
}